// round 6
// baseline (speedup 1.0000x reference)
#include <cuda_runtime.h>
#include <cuda_fp16.h>
#include <math.h>

#define NNODES 100000
#define NEDGES 1600000
#define FDIM   128

// ---------------- scratch ----------------
__device__ __half g_hh[NNODES * FDIM];   // GEMM output in fp16 (gather path)
__device__ float  g_feat[NNODES * FDIM]; // layer-1 activations (fp32, GEMM2 input)
__device__ float  g_as[NNODES * 4];
__device__ float  g_ad[NNODES * 4];
__device__ int    g_cnt[NNODES];
__device__ int    g_rp[NNODES + 1];
__device__ int    g_cursor[NNODES];
__device__ int    g_bsum[64];
__device__ int    g_csr[NEDGES];

// ---------------- f32x2 helpers (sm_103a packed fp32) ----------------
__device__ __forceinline__ unsigned long long pack2(float x) {
    unsigned long long r;
    asm("mov.b64 %0, {%1, %1};" : "=l"(r) : "r"(__float_as_uint(x)));
    return r;
}
#define FMA2(d, a, b) asm("fma.rn.f32x2 %0, %1, %2, %0;" : "+l"(d) : "l"(a), "l"(b))
__device__ __forceinline__ void unpack2(unsigned long long p, float& lo, float& hi) {
    asm("mov.b64 {%0, %1}, %2;" : "=f"(lo), "=f"(hi) : "l"(p));
}

// ---------------- GEMM + fused alpha epilogue; fp16 feature output ----------------
template <int H>
__global__ void gemm_alpha_kernel(const float* __restrict__ A,
                                  const float* __restrict__ W,
                                  __half* __restrict__ hh, int M,
                                  const float* __restrict__ a_src,
                                  const float* __restrict__ a_dst,
                                  float* __restrict__ as_, float* __restrict__ ad_) {
    __shared__ float As[128 * 66];
    int tid  = threadIdx.x;
    int row0 = blockIdx.x * 64;
    int tx = tid & 31;
    int ty = tid >> 5;

    #pragma unroll
    for (int i = 0; i < 8; i++) {
        int idx = tid + 256 * i;
        int r   = idx >> 5;
        int c4  = idx & 31;
        float4 v = make_float4(0.f, 0.f, 0.f, 0.f);
        if (row0 + r < M) v = ((const float4*)A)[(size_t)(row0 + r) * 32 + c4];
        int c = c4 * 4;
        As[(c + 0) * 66 + r] = v.x;
        As[(c + 1) * 66 + r] = v.y;
        As[(c + 2) * 66 + r] = v.z;
        As[(c + 3) * 66 + r] = v.w;
    }
    __syncthreads();

    unsigned long long acc[4][4];
    #pragma unroll
    for (int p = 0; p < 4; p++)
        #pragma unroll
        for (int c = 0; c < 4; c++) acc[p][c] = 0ull;

    const float* asbase = As + ty * 8;
    #pragma unroll 4
    for (int k = 0; k < 128; k++) {
        float4 w = __ldg(&((const float4*)(W + k * 128))[tx]);
        unsigned long long w0 = pack2(w.x), w1 = pack2(w.y),
                           w2 = pack2(w.z), w3 = pack2(w.w);
        const unsigned long long* ap =
            (const unsigned long long*)(asbase + k * 66);
        unsigned long long a0 = ap[0], a1 = ap[1], a2 = ap[2], a3 = ap[3];
        FMA2(acc[0][0], a0, w0); FMA2(acc[0][1], a0, w1);
        FMA2(acc[0][2], a0, w2); FMA2(acc[0][3], a0, w3);
        FMA2(acc[1][0], a1, w0); FMA2(acc[1][1], a1, w1);
        FMA2(acc[1][2], a1, w2); FMA2(acc[1][3], a1, w3);
        FMA2(acc[2][0], a2, w0); FMA2(acc[2][1], a2, w1);
        FMA2(acc[2][2], a2, w2); FMA2(acc[2][3], a2, w3);
        FMA2(acc[3][0], a3, w0); FMA2(acc[3][1], a3, w1);
        FMA2(acc[3][2], a3, w2); FMA2(acc[3][3], a3, w3);
    }

    float4 s4 = ((const float4*)a_src)[tx];
    float4 d4 = ((const float4*)a_dst)[tx];
    const int G = 32 / H;

    #pragma unroll
    for (int p = 0; p < 4; p++) {
        float lo[4], hi[4];
        #pragma unroll
        for (int c = 0; c < 4; c++) unpack2(acc[p][c], lo[c], hi[c]);

        #pragma unroll
        for (int half = 0; half < 2; half++) {
            float* v = half ? hi : lo;
            int row = row0 + ty * 8 + p * 2 + half;
            bool ok = row < M;
            if (ok) {
                __half2 h01 = __floats2half2_rn(v[0], v[1]);
                __half2 h23 = __floats2half2_rn(v[2], v[3]);
                uint2 pk;
                pk.x = *(unsigned int*)&h01;
                pk.y = *(unsigned int*)&h23;
                ((uint2*)hh)[(size_t)row * 32 + tx] = pk;
            }
            float s = v[0] * s4.x + v[1] * s4.y + v[2] * s4.z + v[3] * s4.w;
            float d = v[0] * d4.x + v[1] * d4.y + v[2] * d4.z + v[3] * d4.w;
            #pragma unroll
            for (int off = G / 2; off > 0; off >>= 1) {
                s += __shfl_xor_sync(0xffffffffu, s, off);
                d += __shfl_xor_sync(0xffffffffu, d, off);
            }
            if (ok && (tx & (G - 1)) == 0) {
                int hd = tx / G;
                as_[row * H + hd] = s;
                ad_[row * H + hd] = d;
            }
        }
    }
}

// ---------------- CSR construction ----------------
__global__ void count_kernel(const int* __restrict__ dst, int* __restrict__ cnt) {
    int e = blockIdx.x * blockDim.x + threadIdx.x;
    if (e < NEDGES) atomicAdd(&cnt[dst[e]], 1);
}

__global__ void scan_local_kernel(const int* __restrict__ cnt,
                                  int* __restrict__ excl, int* __restrict__ bsum) {
    __shared__ int sh[512];
    int t = threadIdx.x;
    int base = blockIdx.x * 4096 + t * 8;
    int v[8];
    int run = 0;
    #pragma unroll
    for (int j = 0; j < 8; j++) {
        int c = (base + j < NNODES) ? cnt[base + j] : 0;
        v[j] = run;
        run += c;
    }
    sh[t] = run;
    __syncthreads();
    for (int off = 1; off < 512; off <<= 1) {
        int x = (t >= off) ? sh[t - off] : 0;
        __syncthreads();
        sh[t] += x;
        __syncthreads();
    }
    int excl_t = sh[t] - run;
    if (t == 511) bsum[blockIdx.x] = sh[511];
    #pragma unroll
    for (int j = 0; j < 8; j++)
        if (base + j < NNODES) excl[base + j] = excl_t + v[j];
}

__global__ void scan_add_kernel(const int* __restrict__ excl, const int* __restrict__ bsum,
                                int* __restrict__ rp, int* __restrict__ cursor, int nb) {
    int i = blockIdx.x * blockDim.x + threadIdx.x;
    if (i <= NNODES) {
        int blk = i >> 12;
        int base = 0;
        for (int j = 0; j < nb; j++)
            if (j < blk) base += bsum[j];
        if (i < NNODES) {
            int v = excl[i] + base;
            rp[i] = v;
            cursor[i] = v;
        } else {
            rp[NNODES] = NEDGES;
        }
    }
}

__global__ void scatter_kernel(const int* __restrict__ src, const int* __restrict__ dst,
                               int* __restrict__ cursor, int* __restrict__ csr) {
    int e = blockIdx.x * blockDim.x + threadIdx.x;
    if (e >= NEDGES) return;
    int p = atomicAdd(&cursor[dst[e]], 1);
    csr[p] = src[e];
}

// ---------------- fused aggregation: pipelined single pass, warp per dst ----------------
// Index prefetch breaks the csr->gather dependency chain; launch bounds force
// >=4 blocks/SM (32 warps) for latency coverage.
template <int H, bool ELU>
__global__ void __launch_bounds__(256, 4)
fused_agg_kernel(const int* __restrict__ rowp, const int* __restrict__ csr,
                 const float* __restrict__ as_, const float* __restrict__ ad_,
                 const __half* __restrict__ hfeat,
                 const float* __restrict__ bias,
                 float* __restrict__ outp) {
    int d    = (blockIdx.x * blockDim.x + threadIdx.x) >> 5;
    int lane = threadIdx.x & 31;
    if (d >= NNODES) return;
    int beg = rowp[d], end = rowp[d + 1];

    const int G = 32 / H;
    const int myh = lane / G;
    float adm = ad_[d * H + myh];
    const uint2* hf = (const uint2*)hfeat;

    // self loop
    float sv = as_[d * H + myh] + adm;
    sv = sv >= 0.f ? sv : 0.2f * sv;
    float ev = __expf(sv);
    float den = ev;
    uint2 rs = hf[(size_t)d * 32 + lane];
    float2 f0 = __half22float2(*(__half2*)&rs.x);
    float2 f1 = __half22float2(*(__half2*)&rs.y);
    float4 acc = make_float4(f0.x * ev, f0.y * ev, f1.x * ev, f1.y * ev);

    int i = beg;
    if (end - beg >= 4) {
        // prime the pipeline
        int s0 = csr[i], s1 = csr[i + 1], s2 = csr[i + 2], s3 = csr[i + 3];
        for (; i + 7 < end; i += 4) {
            // prefetch next group's indices (overlaps this group's gathers)
            int t0 = csr[i + 4], t1 = csr[i + 5], t2 = csr[i + 6], t3 = csr[i + 7];
            // issue all 8 data loads up front
            float v0 = as_[s0 * H + myh];
            float v1 = as_[s1 * H + myh];
            float v2 = as_[s2 * H + myh];
            float v3 = as_[s3 * H + myh];
            uint2 r0 = hf[(size_t)s0 * 32 + lane];
            uint2 r1 = hf[(size_t)s1 * 32 + lane];
            uint2 r2 = hf[(size_t)s2 * 32 + lane];
            uint2 r3 = hf[(size_t)s3 * 32 + lane];
            v0 += adm; v1 += adm; v2 += adm; v3 += adm;
            v0 = v0 >= 0.f ? v0 : 0.2f * v0;
            v1 = v1 >= 0.f ? v1 : 0.2f * v1;
            v2 = v2 >= 0.f ? v2 : 0.2f * v2;
            v3 = v3 >= 0.f ? v3 : 0.2f * v3;
            float e0 = __expf(v0), e1 = __expf(v1), e2 = __expf(v2), e3 = __expf(v3);
            den += (e0 + e1) + (e2 + e3);
            float2 a0 = __half22float2(*(__half2*)&r0.x), b0 = __half22float2(*(__half2*)&r0.y);
            float2 a1 = __half22float2(*(__half2*)&r1.x), b1 = __half22float2(*(__half2*)&r1.y);
            float2 a2 = __half22float2(*(__half2*)&r2.x), b2 = __half22float2(*(__half2*)&r2.y);
            float2 a3 = __half22float2(*(__half2*)&r3.x), b3 = __half22float2(*(__half2*)&r3.y);
            acc.x += a0.x * e0 + a1.x * e1 + a2.x * e2 + a3.x * e3;
            acc.y += a0.y * e0 + a1.y * e1 + a2.y * e2 + a3.y * e3;
            acc.z += b0.x * e0 + b1.x * e1 + b2.x * e2 + b3.x * e3;
            acc.w += b0.y * e0 + b1.y * e1 + b2.y * e2 + b3.y * e3;
            s0 = t0; s1 = t1; s2 = t2; s3 = t3;
        }
        // drain: last full group (indices already loaded)
        {
            float v0 = as_[s0 * H + myh];
            float v1 = as_[s1 * H + myh];
            float v2 = as_[s2 * H + myh];
            float v3 = as_[s3 * H + myh];
            uint2 r0 = hf[(size_t)s0 * 32 + lane];
            uint2 r1 = hf[(size_t)s1 * 32 + lane];
            uint2 r2 = hf[(size_t)s2 * 32 + lane];
            uint2 r3 = hf[(size_t)s3 * 32 + lane];
            v0 += adm; v1 += adm; v2 += adm; v3 += adm;
            v0 = v0 >= 0.f ? v0 : 0.2f * v0;
            v1 = v1 >= 0.f ? v1 : 0.2f * v1;
            v2 = v2 >= 0.f ? v2 : 0.2f * v2;
            v3 = v3 >= 0.f ? v3 : 0.2f * v3;
            float e0 = __expf(v0), e1 = __expf(v1), e2 = __expf(v2), e3 = __expf(v3);
            den += (e0 + e1) + (e2 + e3);
            float2 a0 = __half22float2(*(__half2*)&r0.x), b0 = __half22float2(*(__half2*)&r0.y);
            float2 a1 = __half22float2(*(__half2*)&r1.x), b1 = __half22float2(*(__half2*)&r1.y);
            float2 a2 = __half22float2(*(__half2*)&r2.x), b2 = __half22float2(*(__half2*)&r2.y);
            float2 a3 = __half22float2(*(__half2*)&r3.x), b3 = __half22float2(*(__half2*)&r3.y);
            acc.x += a0.x * e0 + a1.x * e1 + a2.x * e2 + a3.x * e3;
            acc.y += a0.y * e0 + a1.y * e1 + a2.y * e2 + a3.y * e3;
            acc.z += b0.x * e0 + b1.x * e1 + b2.x * e2 + b3.x * e3;
            acc.w += b0.y * e0 + b1.y * e1 + b2.y * e2 + b3.y * e3;
            i += 4;
        }
    }
    for (; i < end; i++) {
        int s0 = csr[i];
        float v0 = as_[s0 * H + myh] + adm;
        v0 = v0 >= 0.f ? v0 : 0.2f * v0;
        float e0 = __expf(v0);
        uint2 r0 = hf[(size_t)s0 * 32 + lane];
        float2 a0 = __half22float2(*(__half2*)&r0.x), b0 = __half22float2(*(__half2*)&r0.y);
        den += e0;
        acc.x += a0.x * e0;
        acc.y += a0.y * e0;
        acc.z += b0.x * e0;
        acc.w += b0.y * e0;
    }

    float inv = 1.f / (den + 1e-16f);
    float4 b = ((const float4*)bias)[lane];
    acc.x = acc.x * inv + b.x;
    acc.y = acc.y * inv + b.y;
    acc.z = acc.z * inv + b.z;
    acc.w = acc.w * inv + b.w;
    if (ELU) {
        acc.x = acc.x > 0.f ? acc.x : expm1f(acc.x);
        acc.y = acc.y > 0.f ? acc.y : expm1f(acc.y);
        acc.z = acc.z > 0.f ? acc.z : expm1f(acc.z);
        acc.w = acc.w > 0.f ? acc.w : expm1f(acc.w);
    }
    ((float4*)outp)[(size_t)d * 32 + lane] = acc;
}

// ---------------- launch ----------------
extern "C" void kernel_launch(void* const* d_in, const int* in_sizes, int n_in,
                              void* d_out, int out_size) {
    const float* x      = (const float*)d_in[0];
    const int*   ei     = (const int*)d_in[1];
    const float* W1     = (const float*)d_in[2];
    const float* a_src1 = (const float*)d_in[3];
    const float* a_dst1 = (const float*)d_in[4];
    const float* b1     = (const float*)d_in[5];
    const float* W2     = (const float*)d_in[6];
    const float* a_src2 = (const float*)d_in[7];
    const float* a_dst2 = (const float*)d_in[8];
    const float* b2     = (const float*)d_in[9];
    float* out = (float*)d_out;

    const int* src = ei;
    const int* dst = ei + NEDGES;

    __half* p_hh;
    float *p_feat, *p_as, *p_ad;
    int *p_cnt, *p_rp, *p_cursor, *p_bsum, *p_csr;
    cudaGetSymbolAddress((void**)&p_hh,     g_hh);
    cudaGetSymbolAddress((void**)&p_feat,   g_feat);
    cudaGetSymbolAddress((void**)&p_as,     g_as);
    cudaGetSymbolAddress((void**)&p_ad,     g_ad);
    cudaGetSymbolAddress((void**)&p_cnt,    g_cnt);
    cudaGetSymbolAddress((void**)&p_rp,     g_rp);
    cudaGetSymbolAddress((void**)&p_cursor, g_cursor);
    cudaGetSymbolAddress((void**)&p_bsum,   g_bsum);
    cudaGetSymbolAddress((void**)&p_csr,    g_csr);

    static cudaStream_t s_side = nullptr;
    static cudaEvent_t  ev_fork = nullptr, ev_join = nullptr;
    if (s_side == nullptr) {
        cudaStreamCreateWithFlags(&s_side, cudaStreamNonBlocking);
        cudaEventCreateWithFlags(&ev_fork, cudaEventDisableTiming);
        cudaEventCreateWithFlags(&ev_join, cudaEventDisableTiming);
    }

    const int NT = 256;
    int gemm_blocks  = (NNODES + 63) / 64;
    int node_warps   = (NNODES * 32 + NT - 1) / NT;
    int node1_blocks = (NNODES + 1 + NT - 1) / NT;
    int edge_blocks  = (NEDGES + NT - 1) / NT;
    int scan_blocks  = (NNODES + 4095) / 4096;

    cudaEventRecord(ev_fork, 0);
    cudaStreamWaitEvent(s_side, ev_fork, 0);

    gemm_alpha_kernel<4><<<gemm_blocks, NT>>>(x, W1, p_hh, NNODES,
                                              a_src1, a_dst1, p_as, p_ad);

    cudaMemsetAsync(p_cnt, 0, NNODES * sizeof(int), s_side);
    count_kernel<<<edge_blocks, NT, 0, s_side>>>(dst, p_cnt);
    scan_local_kernel<<<scan_blocks, 512, 0, s_side>>>(p_cnt, p_cnt, p_bsum);
    scan_add_kernel<<<node1_blocks, NT, 0, s_side>>>(p_cnt, p_bsum, p_rp, p_cursor, scan_blocks);
    scatter_kernel<<<edge_blocks, NT, 0, s_side>>>(src, dst, p_cursor, p_csr);
    cudaEventRecord(ev_join, s_side);
    cudaStreamWaitEvent(0, ev_join, 0);

    fused_agg_kernel<4, true><<<node_warps, NT>>>(p_rp, p_csr, p_as, p_ad, p_hh, b1, p_feat);

    gemm_alpha_kernel<1><<<gemm_blocks, NT>>>(p_feat, W2, p_hh, NNODES,
                                              a_src2, a_dst2, p_as, p_ad);
    fused_agg_kernel<1, false><<<node_warps, NT>>>(p_rp, p_csr, p_as, p_ad, p_hh, b2, out);
}